// round 1
// baseline (speedup 1.0000x reference)
#include <cuda_runtime.h>
#include <math.h>

// Problem constants
#define B_ 8
#define S_ 2048
#define D_ 1024
#define M_ (B_ * S_)   // 16384 total rows

// Scratch buffers (allocation-free rule: __device__ globals)
__device__ float g_Q[(size_t)M_ * D_];          // 64 MB
__device__ float g_K[(size_t)M_ * D_];          // 64 MB
__device__ float g_V[(size_t)M_ * D_];          // 64 MB
__device__ float g_P[(size_t)B_ * S_ * S_];     // 134 MB (scores, then probs in-place)

// Tiling
#define BM 128
#define BN 128
#define BK 16
#define NT 256

// ---------------------------------------------------------------------------
// QKV projection: O = x @ W for W in {Wq, Wk, Wv}, selected by blockIdx.z
// x: [M_, D_] row-major, W: [D_, D_] row-major, O: [M_, D_]
// ---------------------------------------------------------------------------
__global__ __launch_bounds__(NT) void proj_kernel(
    const float* __restrict__ x,
    const float* __restrict__ Wq,
    const float* __restrict__ Wk,
    const float* __restrict__ Wv)
{
    __shared__ float As[BK][BM];
    __shared__ float Bs[BK][BN];

    const float* W;
    float* O;
    if (blockIdx.z == 0)      { W = Wq; O = g_Q; }
    else if (blockIdx.z == 1) { W = Wk; O = g_K; }
    else                      { W = Wv; O = g_V; }

    const int tid = threadIdx.x;
    const int ty = tid >> 4;      // 0..15
    const int tx = tid & 15;      // 0..15
    const size_t m0 = (size_t)blockIdx.y * BM;
    const int n0 = blockIdx.x * BN;
    const float* Ap = x + m0 * D_;

    float acc[8][8];
#pragma unroll
    for (int i = 0; i < 8; i++)
#pragma unroll
        for (int j = 0; j < 8; j++) acc[i][j] = 0.f;

    for (int k0 = 0; k0 < D_; k0 += BK) {
        // Load A tile [BM x BK], store transposed As[k][m]
#pragma unroll
        for (int l = 0; l < 2; l++) {
            int idx = tid * 2 + l;          // 0..511
            int row = idx >> 2;             // 0..127
            int c4  = (idx & 3) * 4;        // 0,4,8,12
            float4 v = *(const float4*)(Ap + (size_t)row * D_ + k0 + c4);
            As[c4 + 0][row] = v.x;
            As[c4 + 1][row] = v.y;
            As[c4 + 2][row] = v.z;
            As[c4 + 3][row] = v.w;
        }
        // Load B tile [BK x BN]
#pragma unroll
        for (int l = 0; l < 2; l++) {
            int idx = tid * 2 + l;          // 0..511
            int row = idx >> 5;             // 0..15
            int c4  = (idx & 31) * 4;       // 0..124
            *(float4*)(&Bs[row][c4]) =
                *(const float4*)(W + (size_t)(k0 + row) * D_ + n0 + c4);
        }
        __syncthreads();

#pragma unroll
        for (int k = 0; k < BK; k++) {
            float a[8], b[8];
            *(float4*)(a)     = *(const float4*)(&As[k][ty * 8]);
            *(float4*)(a + 4) = *(const float4*)(&As[k][ty * 8 + 4]);
            *(float4*)(b)     = *(const float4*)(&Bs[k][tx * 8]);
            *(float4*)(b + 4) = *(const float4*)(&Bs[k][tx * 8 + 4]);
#pragma unroll
            for (int i = 0; i < 8; i++)
#pragma unroll
                for (int j = 0; j < 8; j++)
                    acc[i][j] = fmaf(a[i], b[j], acc[i][j]);
        }
        __syncthreads();
    }

    float* Op = O + (m0 + ty * 8) * D_ + n0 + tx * 8;
#pragma unroll
    for (int i = 0; i < 8; i++) {
        *(float4*)(Op + (size_t)i * D_)     = *(float4*)(&acc[i][0]);
        *(float4*)(Op + (size_t)i * D_ + 4) = *(float4*)(&acc[i][4]);
    }
}

// ---------------------------------------------------------------------------
// Scores: S[b, i, j] = inv_scale * dot(Q[b,i,:], K[b,j,:])   (NT GEMM)
// Causal block skip: entire block masked iff nblk > mblk (BM == BN).
// Masked entries inside the diagonal block are computed but never read.
// ---------------------------------------------------------------------------
__global__ __launch_bounds__(NT) void scores_kernel()
{
    const int nblk = blockIdx.x;
    const int mblk = blockIdx.y;
    const int b    = blockIdx.z;
    if (nblk > mblk) return;

    __shared__ float As[BK][BM];
    __shared__ float Bs[BK][BN];

    const float* Qb = g_Q + (size_t)b * S_ * D_ + (size_t)mblk * BM * D_;
    const float* Kb = g_K + (size_t)b * S_ * D_ + (size_t)nblk * BN * D_;

    const int tid = threadIdx.x;
    const int ty = tid >> 4;
    const int tx = tid & 15;

    float acc[8][8];
#pragma unroll
    for (int i = 0; i < 8; i++)
#pragma unroll
        for (int j = 0; j < 8; j++) acc[i][j] = 0.f;

    for (int k0 = 0; k0 < D_; k0 += BK) {
        // Both operands are [rows, D_] row-major -> same transposed-load pattern
#pragma unroll
        for (int l = 0; l < 2; l++) {
            int idx = tid * 2 + l;
            int row = idx >> 2;
            int c4  = (idx & 3) * 4;
            float4 va = *(const float4*)(Qb + (size_t)row * D_ + k0 + c4);
            As[c4 + 0][row] = va.x;
            As[c4 + 1][row] = va.y;
            As[c4 + 2][row] = va.z;
            As[c4 + 3][row] = va.w;
            float4 vb = *(const float4*)(Kb + (size_t)row * D_ + k0 + c4);
            Bs[c4 + 0][row] = vb.x;
            Bs[c4 + 1][row] = vb.y;
            Bs[c4 + 2][row] = vb.z;
            Bs[c4 + 3][row] = vb.w;
        }
        __syncthreads();

#pragma unroll
        for (int k = 0; k < BK; k++) {
            float a[8], bb[8];
            *(float4*)(a)      = *(const float4*)(&As[k][ty * 8]);
            *(float4*)(a + 4)  = *(const float4*)(&As[k][ty * 8 + 4]);
            *(float4*)(bb)     = *(const float4*)(&Bs[k][tx * 8]);
            *(float4*)(bb + 4) = *(const float4*)(&Bs[k][tx * 8 + 4]);
#pragma unroll
            for (int i = 0; i < 8; i++)
#pragma unroll
                for (int j = 0; j < 8; j++)
                    acc[i][j] = fmaf(a[i], bb[j], acc[i][j]);
        }
        __syncthreads();
    }

    const float inv_scale = 0.03125f;  // 1/sqrt(1024)
    float* Sp = g_P + ((size_t)b * S_ + (size_t)mblk * BM + ty * 8) * S_
                + nblk * BN + tx * 8;
#pragma unroll
    for (int i = 0; i < 8; i++) {
        float4 v0, v1;
        v0.x = acc[i][0] * inv_scale; v0.y = acc[i][1] * inv_scale;
        v0.z = acc[i][2] * inv_scale; v0.w = acc[i][3] * inv_scale;
        v1.x = acc[i][4] * inv_scale; v1.y = acc[i][5] * inv_scale;
        v1.z = acc[i][6] * inv_scale; v1.w = acc[i][7] * inv_scale;
        *(float4*)(Sp + (size_t)i * S_)     = v0;
        *(float4*)(Sp + (size_t)i * S_ + 4) = v1;
    }
}

// ---------------------------------------------------------------------------
// Row softmax over valid prefix [0, i], write zeros for j > i (full row).
// One 256-thread block per row. In-place on g_P.
// ---------------------------------------------------------------------------
__global__ __launch_bounds__(256) void softmax_kernel()
{
    const int row = blockIdx.x;          // 0..M_-1  (= b*S_ + i)
    const int i = row & (S_ - 1);
    float* Sr = g_P + (size_t)row * S_;
    const int L = i + 1;
    const int tid = threadIdx.x;

    __shared__ float red[32];

    // --- max over [0, L) ---
    float m = -INFINITY;
    for (int j = tid; j < L; j += 256) m = fmaxf(m, Sr[j]);
#pragma unroll
    for (int o = 16; o; o >>= 1) m = fmaxf(m, __shfl_xor_sync(0xffffffffu, m, o));
    if ((tid & 31) == 0) red[tid >> 5] = m;
    __syncthreads();
    if (tid < 32) {
        float v = (tid < 8) ? red[tid] : -INFINITY;
#pragma unroll
        for (int o = 4; o; o >>= 1) v = fmaxf(v, __shfl_xor_sync(0xffffffffu, v, o));
        if (tid == 0) red[0] = v;
    }
    __syncthreads();
    m = red[0];
    __syncthreads();

    // --- sum of exp over [0, L) ---
    float s = 0.f;
    for (int j = tid; j < L; j += 256) s += __expf(Sr[j] - m);
#pragma unroll
    for (int o = 16; o; o >>= 1) s += __shfl_xor_sync(0xffffffffu, s, o);
    if ((tid & 31) == 0) red[tid >> 5] = s;
    __syncthreads();
    if (tid < 32) {
        float v = (tid < 8) ? red[tid] : 0.f;
#pragma unroll
        for (int o = 4; o; o >>= 1) v += __shfl_xor_sync(0xffffffffu, v, o);
        if (tid == 0) red[0] = v;
    }
    __syncthreads();
    const float inv = 1.f / red[0];

    // --- normalize prefix, zero the rest of the full row ---
    for (int j = tid; j < S_; j += 256) {
        if (j < L) Sr[j] = __expf(Sr[j] - m) * inv;
        else       Sr[j] = 0.f;
    }
}

// ---------------------------------------------------------------------------
// PV: O[b] = P[b] @ V[b]    (NN GEMM, A = P [S_,S_], B = V [S_,D_])
// Causal k-extent: only key blocks <= query block contribute.
// ---------------------------------------------------------------------------
__global__ __launch_bounds__(NT) void pv_kernel(float* __restrict__ out)
{
    const int nblk = blockIdx.x;
    const int mblk = blockIdx.y;
    const int b    = blockIdx.z;

    __shared__ float As[BK][BM];
    __shared__ float Bs[BK][BN];

    const float* Pb = g_P + (size_t)b * S_ * S_ + (size_t)mblk * BM * S_;
    const float* Vb = g_V + (size_t)b * S_ * D_;
    const int n0 = nblk * BN;
    const int kmax = (mblk + 1) * BM;  // causal: P[., j>=kmax] == 0 for this block

    const int tid = threadIdx.x;
    const int ty = tid >> 4;
    const int tx = tid & 15;

    float acc[8][8];
#pragma unroll
    for (int i = 0; i < 8; i++)
#pragma unroll
        for (int j = 0; j < 8; j++) acc[i][j] = 0.f;

    for (int k0 = 0; k0 < kmax; k0 += BK) {
#pragma unroll
        for (int l = 0; l < 2; l++) {
            int idx = tid * 2 + l;
            int row = idx >> 2;
            int c4  = (idx & 3) * 4;
            float4 v = *(const float4*)(Pb + (size_t)row * S_ + k0 + c4);
            As[c4 + 0][row] = v.x;
            As[c4 + 1][row] = v.y;
            As[c4 + 2][row] = v.z;
            As[c4 + 3][row] = v.w;
        }
#pragma unroll
        for (int l = 0; l < 2; l++) {
            int idx = tid * 2 + l;
            int row = idx >> 5;
            int c4  = (idx & 31) * 4;
            *(float4*)(&Bs[row][c4]) =
                *(const float4*)(Vb + (size_t)(k0 + row) * D_ + n0 + c4);
        }
        __syncthreads();

#pragma unroll
        for (int k = 0; k < BK; k++) {
            float a[8], bb[8];
            *(float4*)(a)      = *(const float4*)(&As[k][ty * 8]);
            *(float4*)(a + 4)  = *(const float4*)(&As[k][ty * 8 + 4]);
            *(float4*)(bb)     = *(const float4*)(&Bs[k][tx * 8]);
            *(float4*)(bb + 4) = *(const float4*)(&Bs[k][tx * 8 + 4]);
#pragma unroll
            for (int i = 0; i < 8; i++)
#pragma unroll
                for (int j = 0; j < 8; j++)
                    acc[i][j] = fmaf(a[i], bb[j], acc[i][j]);
        }
        __syncthreads();
    }

    float* Op = out + ((size_t)b * S_ + (size_t)mblk * BM + ty * 8) * D_
                + n0 + tx * 8;
#pragma unroll
    for (int i = 0; i < 8; i++) {
        *(float4*)(Op + (size_t)i * D_)     = *(float4*)(&acc[i][0]);
        *(float4*)(Op + (size_t)i * D_ + 4) = *(float4*)(&acc[i][4]);
    }
}

// ---------------------------------------------------------------------------
extern "C" void kernel_launch(void* const* d_in, const int* in_sizes, int n_in,
                              void* d_out, int out_size)
{
    (void)in_sizes; (void)n_in; (void)out_size;
    const float* x  = (const float*)d_in[0];
    const float* Wq = (const float*)d_in[1];
    const float* Wk = (const float*)d_in[2];
    const float* Wv = (const float*)d_in[3];
    float* out = (float*)d_out;

    dim3 gp(D_ / BN, M_ / BM, 3);
    proj_kernel<<<gp, NT>>>(x, Wq, Wk, Wv);

    dim3 gs(S_ / BN, S_ / BM, B_);
    scores_kernel<<<gs, NT>>>();

    softmax_kernel<<<M_, 256>>>();

    dim3 gv(D_ / BN, S_ / BM, B_);
    pv_kernel<<<gv, NT>>>(out);
}

// round 2
// speedup vs baseline: 3.0316x; 3.0316x over previous
#include <cuda_runtime.h>
#include <math.h>

// Problem constants
#define B_ 8
#define S_ 2048
#define D_ 1024
#define M_ (B_ * S_)   // 16384 total rows

// Scratch buffers (allocation-free rule: __device__ globals)
__device__ float g_Q[(size_t)M_ * D_];          // 64 MB
__device__ float g_K[(size_t)M_ * D_];          // 64 MB
__device__ float g_V[(size_t)M_ * D_];          // 64 MB
__device__ float g_P[(size_t)B_ * S_ * S_];     // 134 MB (scores, then probs in-place)

// Tiling
#define BM 128
#define BN 128
#define BK 32
#define NT 256

// SMEM strides (in 32-bit words), chosen for conflict-free access
#define AS_STR 36    // A tile: [BM][AS_STR], m-major, k contiguous
#define BS_STR 136   // B tile (k-major): [BK][BS_STR], n contiguous
#define BN_STR 36    // B tile (n-major, scores): [BN][BN_STR], k contiguous

__device__ __forceinline__ unsigned f2tf32(float f) {
    unsigned u;
    asm("cvt.rna.tf32.f32 %0, %1;" : "=r"(u) : "f"(f));
    return u;
}

__device__ __forceinline__ void mma_tf32(float c[4],
                                         unsigned a0, unsigned a1, unsigned a2, unsigned a3,
                                         unsigned b0, unsigned b1) {
    asm volatile(
        "mma.sync.aligned.m16n8k8.row.col.f32.tf32.tf32.f32 "
        "{%0,%1,%2,%3}, {%4,%5,%6,%7}, {%8,%9}, {%0,%1,%2,%3};"
        : "+f"(c[0]), "+f"(c[1]), "+f"(c[2]), "+f"(c[3])
        : "r"(a0), "r"(a1), "r"(a2), "r"(a3), "r"(b0), "r"(b1));
}

// ---------------------------------------------------------------------------
// Shared inner loop macros for the warp-tile MMA (8 warps: 4 in M x 2 in N)
// Warp tile: 32 (M) x 64 (N); mi in {0,1}, ni in 0..7
// ---------------------------------------------------------------------------

// ---------------------------------------------------------------------------
// QKV projection: O = x @ W, W selected by blockIdx.z
// x: [M_, D_] row-major, W: [D_, D_] row-major
// ---------------------------------------------------------------------------
__global__ __launch_bounds__(NT) void proj_kernel(
    const float* __restrict__ x,
    const float* __restrict__ Wq,
    const float* __restrict__ Wk,
    const float* __restrict__ Wv)
{
    __shared__ unsigned As[BM * AS_STR];
    __shared__ unsigned Bs[BK * BS_STR];

    const float* W;
    float* O;
    if (blockIdx.z == 0)      { W = Wq; O = g_Q; }
    else if (blockIdx.z == 1) { W = Wk; O = g_K; }
    else                      { W = Wv; O = g_V; }

    const int tid = threadIdx.x;
    const int lane = tid & 31;
    const int wid = tid >> 5;
    const int warp_m = wid & 3;        // 0..3 -> m offset *32
    const int warp_n = wid >> 2;       // 0..1 -> n offset *64
    const int lq = lane >> 2;          // 0..7
    const int lr = lane & 3;           // 0..3

    const size_t m0 = (size_t)blockIdx.y * BM;
    const int n0 = blockIdx.x * BN;
    const float* Ap = x + m0 * D_;

    float acc[2][8][4];
#pragma unroll
    for (int i = 0; i < 2; i++)
#pragma unroll
        for (int j = 0; j < 8; j++)
#pragma unroll
            for (int r = 0; r < 4; r++) acc[i][j][r] = 0.f;

    for (int k0 = 0; k0 < D_; k0 += BK) {
        // A tile: 128x32 floats = 1024 float4, 4 per thread
#pragma unroll
        for (int l = 0; l < 4; l++) {
            int f = tid + l * 256;
            int row = f >> 3;
            int c4 = (f & 7) << 2;
            float4 v = *(const float4*)(Ap + (size_t)row * D_ + k0 + c4);
            uint4 u = {f2tf32(v.x), f2tf32(v.y), f2tf32(v.z), f2tf32(v.w)};
            *(uint4*)(&As[row * AS_STR + c4]) = u;
        }
        // B tile: 32x128 floats, k-major
#pragma unroll
        for (int l = 0; l < 4; l++) {
            int f = tid + l * 256;
            int k = f >> 5;
            int c4 = (f & 31) << 2;
            float4 v = *(const float4*)(W + (size_t)(k0 + k) * D_ + n0 + c4);
            uint4 u = {f2tf32(v.x), f2tf32(v.y), f2tf32(v.z), f2tf32(v.w)};
            *(uint4*)(&Bs[k * BS_STR + c4]) = u;
        }
        __syncthreads();

#pragma unroll
        for (int kk = 0; kk < BK; kk += 8) {
            unsigned af[2][4];
#pragma unroll
            for (int mi = 0; mi < 2; mi++) {
                int bm = warp_m * 32 + mi * 16;
                af[mi][0] = As[(bm + lq) * AS_STR + kk + lr];
                af[mi][1] = As[(bm + lq + 8) * AS_STR + kk + lr];
                af[mi][2] = As[(bm + lq) * AS_STR + kk + lr + 4];
                af[mi][3] = As[(bm + lq + 8) * AS_STR + kk + lr + 4];
            }
#pragma unroll
            for (int ni = 0; ni < 8; ni++) {
                int n = warp_n * 64 + ni * 8 + lq;
                unsigned b0 = Bs[(kk + lr) * BS_STR + n];
                unsigned b1 = Bs[(kk + lr + 4) * BS_STR + n];
#pragma unroll
                for (int mi = 0; mi < 2; mi++)
                    mma_tf32(acc[mi][ni], af[mi][0], af[mi][1], af[mi][2], af[mi][3], b0, b1);
            }
        }
        __syncthreads();
    }

    // Epilogue
#pragma unroll
    for (int mi = 0; mi < 2; mi++) {
        size_t row0 = m0 + warp_m * 32 + mi * 16 + lq;
#pragma unroll
        for (int ni = 0; ni < 8; ni++) {
            int nb = n0 + warp_n * 64 + ni * 8 + lr * 2;
            *(float2*)(O + row0 * D_ + nb) = make_float2(acc[mi][ni][0], acc[mi][ni][1]);
            *(float2*)(O + (row0 + 8) * D_ + nb) = make_float2(acc[mi][ni][2], acc[mi][ni][3]);
        }
    }
}

// ---------------------------------------------------------------------------
// Scores: S[b,i,j] = inv_scale * dot(Q[b,i,:], K[b,j,:])
// B operand (K matrix) loaded n-major so global loads vectorize along k.
// Causal block skip.
// ---------------------------------------------------------------------------
__global__ __launch_bounds__(NT) void scores_kernel()
{
    const int nblk = blockIdx.x;
    const int mblk = blockIdx.y;
    const int b    = blockIdx.z;
    if (nblk > mblk) return;

    __shared__ unsigned As[BM * AS_STR];
    __shared__ unsigned Bsn[BN * BN_STR];   // n-major: [n][k]

    const float* Qb = g_Q + (size_t)b * S_ * D_ + (size_t)mblk * BM * D_;
    const float* Kb = g_K + (size_t)b * S_ * D_ + (size_t)nblk * BN * D_;

    const int tid = threadIdx.x;
    const int lane = tid & 31;
    const int wid = tid >> 5;
    const int warp_m = wid & 3;
    const int warp_n = wid >> 2;
    const int lq = lane >> 2;
    const int lr = lane & 3;

    float acc[2][8][4];
#pragma unroll
    for (int i = 0; i < 2; i++)
#pragma unroll
        for (int j = 0; j < 8; j++)
#pragma unroll
            for (int r = 0; r < 4; r++) acc[i][j][r] = 0.f;

    for (int k0 = 0; k0 < D_; k0 += BK) {
#pragma unroll
        for (int l = 0; l < 4; l++) {
            int f = tid + l * 256;
            int row = f >> 3;
            int c4 = (f & 7) << 2;
            float4 v = *(const float4*)(Qb + (size_t)row * D_ + k0 + c4);
            uint4 u = {f2tf32(v.x), f2tf32(v.y), f2tf32(v.z), f2tf32(v.w)};
            *(uint4*)(&As[row * AS_STR + c4]) = u;
            float4 w = *(const float4*)(Kb + (size_t)row * D_ + k0 + c4);
            uint4 u2 = {f2tf32(w.x), f2tf32(w.y), f2tf32(w.z), f2tf32(w.w)};
            *(uint4*)(&Bsn[row * BN_STR + c4]) = u2;
        }
        __syncthreads();

#pragma unroll
        for (int kk = 0; kk < BK; kk += 8) {
            unsigned af[2][4];
#pragma unroll
            for (int mi = 0; mi < 2; mi++) {
                int bm = warp_m * 32 + mi * 16;
                af[mi][0] = As[(bm + lq) * AS_STR + kk + lr];
                af[mi][1] = As[(bm + lq + 8) * AS_STR + kk + lr];
                af[mi][2] = As[(bm + lq) * AS_STR + kk + lr + 4];
                af[mi][3] = As[(bm + lq + 8) * AS_STR + kk + lr + 4];
            }
#pragma unroll
            for (int ni = 0; ni < 8; ni++) {
                int n = warp_n * 64 + ni * 8 + lq;
                unsigned b0 = Bsn[n * BN_STR + kk + lr];
                unsigned b1 = Bsn[n * BN_STR + kk + lr + 4];
#pragma unroll
                for (int mi = 0; mi < 2; mi++)
                    mma_tf32(acc[mi][ni], af[mi][0], af[mi][1], af[mi][2], af[mi][3], b0, b1);
            }
        }
        __syncthreads();
    }

    const float inv_scale = 0.03125f;  // 1/sqrt(1024)
#pragma unroll
    for (int mi = 0; mi < 2; mi++) {
        size_t row0 = (size_t)b * S_ + (size_t)mblk * BM + warp_m * 32 + mi * 16 + lq;
#pragma unroll
        for (int ni = 0; ni < 8; ni++) {
            int nb = nblk * BN + warp_n * 64 + ni * 8 + lr * 2;
            *(float2*)(g_P + row0 * S_ + nb) =
                make_float2(acc[mi][ni][0] * inv_scale, acc[mi][ni][1] * inv_scale);
            *(float2*)(g_P + (row0 + 8) * S_ + nb) =
                make_float2(acc[mi][ni][2] * inv_scale, acc[mi][ni][3] * inv_scale);
        }
    }
}

// ---------------------------------------------------------------------------
// Row softmax over valid prefix [0, i], zeros elsewhere. In-place on g_P.
// ---------------------------------------------------------------------------
__global__ __launch_bounds__(256) void softmax_kernel()
{
    const int row = blockIdx.x;
    const int i = row & (S_ - 1);
    float* Sr = g_P + (size_t)row * S_;
    const int L = i + 1;
    const int tid = threadIdx.x;

    __shared__ float red[32];

    float m = -INFINITY;
    for (int j = tid; j < L; j += 256) m = fmaxf(m, Sr[j]);
#pragma unroll
    for (int o = 16; o; o >>= 1) m = fmaxf(m, __shfl_xor_sync(0xffffffffu, m, o));
    if ((tid & 31) == 0) red[tid >> 5] = m;
    __syncthreads();
    if (tid < 32) {
        float v = (tid < 8) ? red[tid] : -INFINITY;
#pragma unroll
        for (int o = 4; o; o >>= 1) v = fmaxf(v, __shfl_xor_sync(0xffffffffu, v, o));
        if (tid == 0) red[0] = v;
    }
    __syncthreads();
    m = red[0];
    __syncthreads();

    float s = 0.f;
    for (int j = tid; j < L; j += 256) s += __expf(Sr[j] - m);
#pragma unroll
    for (int o = 16; o; o >>= 1) s += __shfl_xor_sync(0xffffffffu, s, o);
    if ((tid & 31) == 0) red[tid >> 5] = s;
    __syncthreads();
    if (tid < 32) {
        float v = (tid < 8) ? red[tid] : 0.f;
#pragma unroll
        for (int o = 4; o; o >>= 1) v += __shfl_xor_sync(0xffffffffu, v, o);
        if (tid == 0) red[0] = v;
    }
    __syncthreads();
    const float inv = 1.f / red[0];

    for (int j = tid; j < S_; j += 256) {
        if (j < L) Sr[j] = __expf(Sr[j] - m) * inv;
        else       Sr[j] = 0.f;
    }
}

// ---------------------------------------------------------------------------
// PV: O[b] = P[b] @ V[b], causal k-extent limit.
// ---------------------------------------------------------------------------
__global__ __launch_bounds__(NT) void pv_kernel(float* __restrict__ out)
{
    const int nblk = blockIdx.x;
    const int mblk = blockIdx.y;
    const int b    = blockIdx.z;

    __shared__ unsigned As[BM * AS_STR];
    __shared__ unsigned Bs[BK * BS_STR];

    const float* Pb = g_P + (size_t)b * S_ * S_ + (size_t)mblk * BM * S_;
    const float* Vb = g_V + (size_t)b * S_ * D_;
    const int n0 = nblk * BN;
    const int kmax = (mblk + 1) * BM;

    const int tid = threadIdx.x;
    const int lane = tid & 31;
    const int wid = tid >> 5;
    const int warp_m = wid & 3;
    const int warp_n = wid >> 2;
    const int lq = lane >> 2;
    const int lr = lane & 3;

    float acc[2][8][4];
#pragma unroll
    for (int i = 0; i < 2; i++)
#pragma unroll
        for (int j = 0; j < 8; j++)
#pragma unroll
            for (int r = 0; r < 4; r++) acc[i][j][r] = 0.f;

    for (int k0 = 0; k0 < kmax; k0 += BK) {
#pragma unroll
        for (int l = 0; l < 4; l++) {
            int f = tid + l * 256;
            int row = f >> 3;
            int c4 = (f & 7) << 2;
            float4 v = *(const float4*)(Pb + (size_t)row * S_ + k0 + c4);
            uint4 u = {f2tf32(v.x), f2tf32(v.y), f2tf32(v.z), f2tf32(v.w)};
            *(uint4*)(&As[row * AS_STR + c4]) = u;
        }
#pragma unroll
        for (int l = 0; l < 4; l++) {
            int f = tid + l * 256;
            int k = f >> 5;
            int c4 = (f & 31) << 2;
            float4 v = *(const float4*)(Vb + (size_t)(k0 + k) * D_ + n0 + c4);
            uint4 u = {f2tf32(v.x), f2tf32(v.y), f2tf32(v.z), f2tf32(v.w)};
            *(uint4*)(&Bs[k * BS_STR + c4]) = u;
        }
        __syncthreads();

#pragma unroll
        for (int kk = 0; kk < BK; kk += 8) {
            unsigned af[2][4];
#pragma unroll
            for (int mi = 0; mi < 2; mi++) {
                int bm = warp_m * 32 + mi * 16;
                af[mi][0] = As[(bm + lq) * AS_STR + kk + lr];
                af[mi][1] = As[(bm + lq + 8) * AS_STR + kk + lr];
                af[mi][2] = As[(bm + lq) * AS_STR + kk + lr + 4];
                af[mi][3] = As[(bm + lq + 8) * AS_STR + kk + lr + 4];
            }
#pragma unroll
            for (int ni = 0; ni < 8; ni++) {
                int n = warp_n * 64 + ni * 8 + lq;
                unsigned b0 = Bs[(kk + lr) * BS_STR + n];
                unsigned b1 = Bs[(kk + lr + 4) * BS_STR + n];
#pragma unroll
                for (int mi = 0; mi < 2; mi++)
                    mma_tf32(acc[mi][ni], af[mi][0], af[mi][1], af[mi][2], af[mi][3], b0, b1);
            }
        }
        __syncthreads();
    }

#pragma unroll
    for (int mi = 0; mi < 2; mi++) {
        size_t row0 = (size_t)b * S_ + (size_t)mblk * BM + warp_m * 32 + mi * 16 + lq;
#pragma unroll
        for (int ni = 0; ni < 8; ni++) {
            int nb = n0 + warp_n * 64 + ni * 8 + lr * 2;
            *(float2*)(out + row0 * D_ + nb) = make_float2(acc[mi][ni][0], acc[mi][ni][1]);
            *(float2*)(out + (row0 + 8) * D_ + nb) = make_float2(acc[mi][ni][2], acc[mi][ni][3]);
        }
    }
}

// ---------------------------------------------------------------------------
extern "C" void kernel_launch(void* const* d_in, const int* in_sizes, int n_in,
                              void* d_out, int out_size)
{
    (void)in_sizes; (void)n_in; (void)out_size;
    const float* x  = (const float*)d_in[0];
    const float* Wq = (const float*)d_in[1];
    const float* Wk = (const float*)d_in[2];
    const float* Wv = (const float*)d_in[3];
    float* out = (float*)d_out;

    dim3 gp(D_ / BN, M_ / BM, 3);
    proj_kernel<<<gp, NT>>>(x, Wq, Wk, Wv);

    dim3 gs(S_ / BN, S_ / BM, B_);
    scores_kernel<<<gs, NT>>>();

    softmax_kernel<<<M_, 256>>>();

    dim3 gv(D_ / BN, S_ / BM, B_);
    pv_kernel<<<gv, NT>>>(out);
}

// round 4
// speedup vs baseline: 3.5885x; 1.1837x over previous
#include <cuda_runtime.h>
#include <math.h>

// Problem constants
#define B_ 8
#define S_ 2048
#define D_ 1024
#define M_ (B_ * S_)   // 16384 total rows

// Scratch buffers (allocation-free rule: __device__ globals)
__device__ float g_X [(size_t)M_ * D_];         // tf32-rounded x
__device__ float g_Wq[(size_t)D_ * D_];
__device__ float g_Wk[(size_t)D_ * D_];
__device__ float g_Wv[(size_t)D_ * D_];
__device__ float g_Q[(size_t)M_ * D_];
__device__ float g_K[(size_t)M_ * D_];
__device__ float g_V[(size_t)M_ * D_];
__device__ float g_P[(size_t)B_ * S_ * S_];     // scores -> probs (tf32-rounded)

// Tiling
#define BM 128
#define BN 128
#define BK 16
#define NT 256
#define STAGES 4

// SMEM strides (32-bit words)
#define AS_STR 20    // A tile [BM][AS_STR], m-major, k contiguous  (BK=16 + pad4)
#define BS_STR 136   // B tile k-major [BK][BS_STR], n contiguous   (BN=128 + pad8)
#define BNM_STR 20   // B tile n-major [BN][BNM_STR], k contiguous

#define A_STG (BM * AS_STR)     // 2560 words
#define BK_STG (BK * BS_STR)    // 2176 words
#define BNM_STG (BN * BNM_STR)  // 2560 words

__device__ __forceinline__ unsigned f2tf32(float f) {
    unsigned u;
    asm("cvt.rna.tf32.f32 %0, %1;" : "=r"(u) : "f"(f));
    return u;
}

__device__ __forceinline__ void cp16(unsigned* smem_dst, const float* gsrc) {
    unsigned s = (unsigned)__cvta_generic_to_shared(smem_dst);
    asm volatile("cp.async.cg.shared.global [%0], [%1], 16;" :: "r"(s), "l"(gsrc));
}
__device__ __forceinline__ void cp_commit() {
    asm volatile("cp.async.commit_group;");
}
template <int N>
__device__ __forceinline__ void cp_wait() {
    asm volatile("cp.async.wait_group %0;" :: "n"(N));
}

__device__ __forceinline__ void mma_tf32(float c[4],
                                         unsigned a0, unsigned a1, unsigned a2, unsigned a3,
                                         unsigned b0, unsigned b1) {
    asm volatile(
        "mma.sync.aligned.m16n8k8.row.col.f32.tf32.tf32.f32 "
        "{%0,%1,%2,%3}, {%4,%5,%6,%7}, {%8,%9}, {%0,%1,%2,%3};"
        : "+f"(c[0]), "+f"(c[1]), "+f"(c[2]), "+f"(c[3])
        : "r"(a0), "r"(a1), "r"(a2), "r"(a3), "r"(b0), "r"(b1));
}

// ---------------------------------------------------------------------------
// Pre-convert: round fp32 -> tf32 bit patterns (rna), elementwise float4.
// ---------------------------------------------------------------------------
__global__ __launch_bounds__(256) void cvt_kernel(const float* __restrict__ src,
                                                  float* __restrict__ dst, int n4)
{
    int i = blockIdx.x * blockDim.x + threadIdx.x;
    if (i < n4) {
        float4 v = ((const float4*)src)[i];
        float4 o;
        o.x = __uint_as_float(f2tf32(v.x));
        o.y = __uint_as_float(f2tf32(v.y));
        o.z = __uint_as_float(f2tf32(v.z));
        o.w = __uint_as_float(f2tf32(v.w));
        ((float4*)dst)[i] = o;
    }
}

// ===========================================================================
// Shared mainloop fragments (8 warps: 4 in M x 2 in N; warp tile 32x64)
// ===========================================================================
#define DECL_IDS \
    const int tid = threadIdx.x;  \
    const int lane = tid & 31;    \
    const int wid = tid >> 5;     \
    const int warp_m = wid & 3;   \
    const int warp_n = wid >> 2;  \
    const int lq = lane >> 2;     \
    const int lr = lane & 3;

#define DECL_ACC \
    float acc[2][8][4]; \
    _Pragma("unroll") for (int i = 0; i < 2; i++) \
    _Pragma("unroll") for (int j = 0; j < 8; j++) \
    _Pragma("unroll") for (int r = 0; r < 4; r++) acc[i][j][r] = 0.f;

// compute one BK=16 stage; As m-major (AS_STR), Bs k-major (BS_STR)
#define COMPUTE_STAGE_KMAJ(Asb, Bsb)                                          \
    _Pragma("unroll")                                                         \
    for (int kk = 0; kk < BK; kk += 8) {                                      \
        unsigned af[2][4];                                                    \
        _Pragma("unroll")                                                     \
        for (int mi = 0; mi < 2; mi++) {                                      \
            int bm = warp_m * 32 + mi * 16;                                   \
            af[mi][0] = (Asb)[(bm + lq) * AS_STR + kk + lr];                  \
            af[mi][1] = (Asb)[(bm + lq + 8) * AS_STR + kk + lr];              \
            af[mi][2] = (Asb)[(bm + lq) * AS_STR + kk + lr + 4];              \
            af[mi][3] = (Asb)[(bm + lq + 8) * AS_STR + kk + lr + 4];          \
        }                                                                     \
        _Pragma("unroll")                                                     \
        for (int ni = 0; ni < 8; ni++) {                                      \
            int n = warp_n * 64 + ni * 8 + lq;                                \
            unsigned b0 = (Bsb)[(kk + lr) * BS_STR + n];                      \
            unsigned b1 = (Bsb)[(kk + lr + 4) * BS_STR + n];                  \
            _Pragma("unroll")                                                 \
            for (int mi = 0; mi < 2; mi++)                                    \
                mma_tf32(acc[mi][ni], af[mi][0], af[mi][1], af[mi][2],        \
                         af[mi][3], b0, b1);                                  \
        }                                                                     \
    }

// compute one stage; Bs n-major (BNM_STR) — for scores (B = K matrix rows)
#define COMPUTE_STAGE_NMAJ(Asb, Bsb)                                          \
    _Pragma("unroll")                                                         \
    for (int kk = 0; kk < BK; kk += 8) {                                      \
        unsigned af[2][4];                                                    \
        _Pragma("unroll")                                                     \
        for (int mi = 0; mi < 2; mi++) {                                      \
            int bm = warp_m * 32 + mi * 16;                                   \
            af[mi][0] = (Asb)[(bm + lq) * AS_STR + kk + lr];                  \
            af[mi][1] = (Asb)[(bm + lq + 8) * AS_STR + kk + lr];              \
            af[mi][2] = (Asb)[(bm + lq) * AS_STR + kk + lr + 4];              \
            af[mi][3] = (Asb)[(bm + lq + 8) * AS_STR + kk + lr + 4];          \
        }                                                                     \
        _Pragma("unroll")                                                     \
        for (int ni = 0; ni < 8; ni++) {                                      \
            int n = warp_n * 64 + ni * 8 + lq;                                \
            unsigned b0 = (Bsb)[n * BNM_STR + kk + lr];                       \
            unsigned b1 = (Bsb)[n * BNM_STR + kk + lr + 4];                   \
            _Pragma("unroll")                                                 \
            for (int mi = 0; mi < 2; mi++)                                    \
                mma_tf32(acc[mi][ni], af[mi][0], af[mi][1], af[mi][2],        \
                         af[mi][3], b0, b1);                                  \
        }                                                                     \
    }

// ---------------------------------------------------------------------------
// QKV projection: O = X @ W (both pre-rounded tf32). Epilogue rounds output.
// ---------------------------------------------------------------------------
__global__ __launch_bounds__(NT, 2) void proj_kernel()
{
    extern __shared__ unsigned smem[];
    unsigned* As = smem;                    // STAGES * A_STG
    unsigned* Bs = smem + STAGES * A_STG;   // STAGES * BK_STG

    const float* W;
    float* O;
    if (blockIdx.z == 0)      { W = g_Wq; O = g_Q; }
    else if (blockIdx.z == 1) { W = g_Wk; O = g_K; }
    else                      { W = g_Wv; O = g_V; }

    DECL_IDS;
    const size_t m0 = (size_t)blockIdx.y * BM;
    const int n0 = blockIdx.x * BN;
    const float* Ap = g_X + m0 * D_;

    const int a_row = tid >> 2;
    const int a_c4  = (tid & 3) << 2;
    const int b_k   = tid >> 5;
    const int b_c4  = (tid & 31) << 2;

#define PROJ_ISSUE(s, k0)                                                     \
    {                                                                         \
        unsigned* Ad = As + (s) * A_STG;                                      \
        unsigned* Bd = Bs + (s) * BK_STG;                                     \
        cp16(Ad + a_row * AS_STR + a_c4, Ap + (size_t)a_row * D_ + (k0) + a_c4); \
        cp16(Ad + (a_row + 64) * AS_STR + a_c4, Ap + (size_t)(a_row + 64) * D_ + (k0) + a_c4); \
        cp16(Bd + b_k * BS_STR + b_c4, W + (size_t)((k0) + b_k) * D_ + n0 + b_c4); \
        cp16(Bd + (b_k + 8) * BS_STR + b_c4, W + (size_t)((k0) + b_k + 8) * D_ + n0 + b_c4); \
        cp_commit();                                                          \
    }

    DECL_ACC;

    const int T = D_ / BK;  // 64
#pragma unroll
    for (int s = 0; s < STAGES - 1; s++) PROJ_ISSUE(s, s * BK);

    for (int it = 0; it < T; it++) {
        cp_wait<STAGES - 2>();
        __syncthreads();
        int sb = it & (STAGES - 1);
        COMPUTE_STAGE_KMAJ(As + sb * A_STG, Bs + sb * BK_STG);
        int nx = it + STAGES - 1;
        if (nx < T) PROJ_ISSUE(nx & (STAGES - 1), nx * BK)
        else        cp_commit();   // empty group: keeps wait_group<2> == "stage it done"
        __syncthreads();
    }
#undef PROJ_ISSUE

    // Epilogue: round to tf32 at store (downstream GEMMs read raw)
#pragma unroll
    for (int mi = 0; mi < 2; mi++) {
        size_t row0 = m0 + warp_m * 32 + mi * 16 + lq;
#pragma unroll
        for (int ni = 0; ni < 8; ni++) {
            int nb = n0 + warp_n * 64 + ni * 8 + lr * 2;
            float2 v0 = make_float2(__uint_as_float(f2tf32(acc[mi][ni][0])),
                                    __uint_as_float(f2tf32(acc[mi][ni][1])));
            float2 v1 = make_float2(__uint_as_float(f2tf32(acc[mi][ni][2])),
                                    __uint_as_float(f2tf32(acc[mi][ni][3])));
            *(float2*)(O + row0 * D_ + nb) = v0;
            *(float2*)(O + (row0 + 8) * D_ + nb) = v1;
        }
    }
}

// ---------------------------------------------------------------------------
// Scores: S = inv_scale * Q @ K^T; K rows copied n-major (direct row copy).
// ---------------------------------------------------------------------------
__global__ __launch_bounds__(NT, 2) void scores_kernel()
{
    const int nblk = blockIdx.x;
    const int mblk = blockIdx.y;
    const int b    = blockIdx.z;
    if (nblk > mblk) return;

    extern __shared__ unsigned smem[];
    unsigned* As  = smem;
    unsigned* Bsn = smem + STAGES * A_STG;

    const float* Qb = g_Q + (size_t)b * S_ * D_ + (size_t)mblk * BM * D_;
    const float* Kb = g_K + (size_t)b * S_ * D_ + (size_t)nblk * BN * D_;

    DECL_IDS;
    const int a_row = tid >> 2;
    const int a_c4  = (tid & 3) << 2;

#define SC_ISSUE(s, k0)                                                       \
    {                                                                         \
        unsigned* Ad = As + (s) * A_STG;                                      \
        unsigned* Bd = Bsn + (s) * BNM_STG;                                   \
        cp16(Ad + a_row * AS_STR + a_c4, Qb + (size_t)a_row * D_ + (k0) + a_c4); \
        cp16(Ad + (a_row + 64) * AS_STR + a_c4, Qb + (size_t)(a_row + 64) * D_ + (k0) + a_c4); \
        cp16(Bd + a_row * BNM_STR + a_c4, Kb + (size_t)a_row * D_ + (k0) + a_c4); \
        cp16(Bd + (a_row + 64) * BNM_STR + a_c4, Kb + (size_t)(a_row + 64) * D_ + (k0) + a_c4); \
        cp_commit();                                                          \
    }

    DECL_ACC;

    const int T = D_ / BK;
#pragma unroll
    for (int s = 0; s < STAGES - 1; s++) SC_ISSUE(s, s * BK);

    for (int it = 0; it < T; it++) {
        cp_wait<STAGES - 2>();
        __syncthreads();
        int sb = it & (STAGES - 1);
        COMPUTE_STAGE_NMAJ(As + sb * A_STG, Bsn + sb * BNM_STG);
        int nx = it + STAGES - 1;
        if (nx < T) SC_ISSUE(nx & (STAGES - 1), nx * BK)
        else        cp_commit();
        __syncthreads();
    }
#undef SC_ISSUE

    const float inv_scale = 0.03125f;  // 1/sqrt(1024)
#pragma unroll
    for (int mi = 0; mi < 2; mi++) {
        size_t row0 = (size_t)b * S_ + (size_t)mblk * BM + warp_m * 32 + mi * 16 + lq;
#pragma unroll
        for (int ni = 0; ni < 8; ni++) {
            int nb = nblk * BN + warp_n * 64 + ni * 8 + lr * 2;
            *(float2*)(g_P + row0 * S_ + nb) =
                make_float2(acc[mi][ni][0] * inv_scale, acc[mi][ni][1] * inv_scale);
            *(float2*)(g_P + (row0 + 8) * S_ + nb) =
                make_float2(acc[mi][ni][2] * inv_scale, acc[mi][ni][3] * inv_scale);
        }
    }
}

// ---------------------------------------------------------------------------
// Row softmax over prefix [0, i]; writes tf32-rounded probs, zeros elsewhere.
// ---------------------------------------------------------------------------
__global__ __launch_bounds__(256) void softmax_kernel()
{
    const int row = blockIdx.x;
    const int i = row & (S_ - 1);
    float* Sr = g_P + (size_t)row * S_;
    const int L = i + 1;
    const int tid = threadIdx.x;

    __shared__ float red[32];

    float m = -INFINITY;
    for (int j = tid; j < L; j += 256) m = fmaxf(m, Sr[j]);
#pragma unroll
    for (int o = 16; o; o >>= 1) m = fmaxf(m, __shfl_xor_sync(0xffffffffu, m, o));
    if ((tid & 31) == 0) red[tid >> 5] = m;
    __syncthreads();
    if (tid < 32) {
        float v = (tid < 8) ? red[tid] : -INFINITY;
#pragma unroll
        for (int o = 4; o; o >>= 1) v = fmaxf(v, __shfl_xor_sync(0xffffffffu, v, o));
        if (tid == 0) red[0] = v;
    }
    __syncthreads();
    m = red[0];
    __syncthreads();

    float s = 0.f;
    for (int j = tid; j < L; j += 256) s += __expf(Sr[j] - m);
#pragma unroll
    for (int o = 16; o; o >>= 1) s += __shfl_xor_sync(0xffffffffu, s, o);
    if ((tid & 31) == 0) red[tid >> 5] = s;
    __syncthreads();
    if (tid < 32) {
        float v = (tid < 8) ? red[tid] : 0.f;
#pragma unroll
        for (int o = 4; o; o >>= 1) v += __shfl_xor_sync(0xffffffffu, v, o);
        if (tid == 0) red[0] = v;
    }
    __syncthreads();
    const float inv = 1.f / red[0];

    for (int j = tid; j < S_; j += 256) {
        if (j < L) Sr[j] = __uint_as_float(f2tf32(__expf(Sr[j] - m) * inv));
        else       Sr[j] = 0.f;
    }
}

// ---------------------------------------------------------------------------
// PV: O = P @ V, causal k-extent limit. Output stays fp32.
// ---------------------------------------------------------------------------
__global__ __launch_bounds__(NT, 2) void pv_kernel(float* __restrict__ out)
{
    const int nblk = blockIdx.x;
    const int mblk = blockIdx.y;
    const int b    = blockIdx.z;

    extern __shared__ unsigned smem[];
    unsigned* As = smem;
    unsigned* Bs = smem + STAGES * A_STG;

    const float* Pb = g_P + (size_t)b * S_ * S_ + (size_t)mblk * BM * S_;
    const float* Vb = g_V + (size_t)b * S_ * D_;
    const int n0 = nblk * BN;
    const int T = (mblk + 1) * (BM / BK);   // k-tiles (>= 8)

    DECL_IDS;
    const int a_row = tid >> 2;
    const int a_c4  = (tid & 3) << 2;
    const int b_k   = tid >> 5;
    const int b_c4  = (tid & 31) << 2;

#define PV_ISSUE(s, k0)                                                       \
    {                                                                         \
        unsigned* Ad = As + (s) * A_STG;                                      \
        unsigned* Bd = Bs + (s) * BK_STG;                                     \
        cp16(Ad + a_row * AS_STR + a_c4, Pb + (size_t)a_row * S_ + (k0) + a_c4); \
        cp16(Ad + (a_row + 64) * AS_STR + a_c4, Pb + (size_t)(a_row + 64) * S_ + (k0) + a_c4); \
        cp16(Bd + b_k * BS_STR + b_c4, Vb + (size_t)((k0) + b_k) * D_ + n0 + b_c4); \
        cp16(Bd + (b_k + 8) * BS_STR + b_c4, Vb + (size_t)((k0) + b_k + 8) * D_ + n0 + b_c4); \
        cp_commit();                                                          \
    }

    DECL_ACC;

#pragma unroll
    for (int s = 0; s < STAGES - 1; s++) PV_ISSUE(s, s * BK);

    for (int it = 0; it < T; it++) {
        cp_wait<STAGES - 2>();
        __syncthreads();
        int sb = it & (STAGES - 1);
        COMPUTE_STAGE_KMAJ(As + sb * A_STG, Bs + sb * BK_STG);
        int nx = it + STAGES - 1;
        if (nx < T) PV_ISSUE(nx & (STAGES - 1), nx * BK)
        else        cp_commit();
        __syncthreads();
    }
#undef PV_ISSUE

#pragma unroll
    for (int mi = 0; mi < 2; mi++) {
        size_t row0 = (size_t)b * S_ + (size_t)mblk * BM + warp_m * 32 + mi * 16 + lq;
#pragma unroll
        for (int ni = 0; ni < 8; ni++) {
            int nb = n0 + warp_n * 64 + ni * 8 + lr * 2;
            *(float2*)(out + row0 * D_ + nb) = make_float2(acc[mi][ni][0], acc[mi][ni][1]);
            *(float2*)(out + (row0 + 8) * D_ + nb) = make_float2(acc[mi][ni][2], acc[mi][ni][3]);
        }
    }
}

// ---------------------------------------------------------------------------
extern "C" void kernel_launch(void* const* d_in, const int* in_sizes, int n_in,
                              void* d_out, int out_size)
{
    (void)in_sizes; (void)n_in; (void)out_size;
    const float* x  = (const float*)d_in[0];
    const float* Wq = (const float*)d_in[1];
    const float* Wk = (const float*)d_in[2];
    const float* Wv = (const float*)d_in[3];
    float* out = (float*)d_out;

    const int SM_PROJ   = STAGES * (A_STG + BK_STG) * 4;   // 75776 B
    const int SM_SCORES = STAGES * (A_STG + BNM_STG) * 4;  // 81920 B
    const int SM_PV     = SM_PROJ;

    cudaFuncSetAttribute(proj_kernel,   cudaFuncAttributeMaxDynamicSharedMemorySize, SM_PROJ);
    cudaFuncSetAttribute(scores_kernel, cudaFuncAttributeMaxDynamicSharedMemorySize, SM_SCORES);
    cudaFuncSetAttribute(pv_kernel,     cudaFuncAttributeMaxDynamicSharedMemorySize, SM_PV);

    // Pre-round inputs to tf32 (rna)
    {
        float* xd;  cudaGetSymbolAddress((void**)&xd,  g_X);
        float* wqd; cudaGetSymbolAddress((void**)&wqd, g_Wq);
        float* wkd; cudaGetSymbolAddress((void**)&wkd, g_Wk);
        float* wvd; cudaGetSymbolAddress((void**)&wvd, g_Wv);
        int nx4 = (M_ * D_) / 4;
        int nw4 = (D_ * D_) / 4;
        cvt_kernel<<<(nx4 + 255) / 256, 256>>>(x,  xd,  nx4);
        cvt_kernel<<<(nw4 + 255) / 256, 256>>>(Wq, wqd, nw4);
        cvt_kernel<<<(nw4 + 255) / 256, 256>>>(Wk, wkd, nw4);
        cvt_kernel<<<(nw4 + 255) / 256, 256>>>(Wv, wvd, nw4);
    }

    dim3 gp(D_ / BN, M_ / BM, 3);
    proj_kernel<<<gp, NT, SM_PROJ>>>();

    dim3 gs(S_ / BN, S_ / BM, B_);
    scores_kernel<<<gs, NT, SM_SCORES>>>();

    softmax_kernel<<<M_, 256>>>();

    dim3 gv(D_ / BN, S_ / BM, B_);
    pv_kernel<<<gv, NT, SM_PV>>>(out);
}